// round 15
// baseline (speedup 1.0000x reference)
#include <cuda_runtime.h>
#include <math.h>

#define S_    2048
#define DM_   768
#define H_    12
#define DK_   64
#define FEAT_ 128
#define J_    4095   /* 2S-1 */

typedef unsigned long long u64;

__device__ __forceinline__ u64 pack2(float lo, float hi) {
    u64 r; asm("mov.b64 %0, {%1, %2};" : "=l"(r) : "f"(lo), "f"(hi)); return r;
}
__device__ __forceinline__ void unpack2(u64 v, float& lo, float& hi) {
    asm("mov.b64 {%0, %1}, %2;" : "=f"(lo), "=f"(hi) : "l"(v));
}
__device__ __forceinline__ void fma2(u64& d, u64 a, u64 b) {
    asm("fma.rn.f32x2 %0, %1, %2, %0;" : "+l"(d) : "l"(a), "l"(b));
}
__device__ __forceinline__ u64 fma2n(u64 a, u64 b, u64 c) {
    u64 d; asm("fma.rn.f32x2 %0, %1, %2, %3;" : "=l"(d) : "l"(a), "l"(b), "l"(c)); return d;
}

// ---------------- scratch (static device globals; referenced ONLY in device code) --
__device__ float g_qh[H_*S_*DK_];
__device__ float g_kh[H_*S_*DK_];
__device__ float g_vh[H_*S_*DK_];
__device__ float g_pe[J_*DM_];
__device__ float g_rk[H_*J_*DK_];
__device__ float g_bw[H_*S_];
__device__ float g_br[H_*J_];
__device__ float g_attn[H_*S_*S_];
__device__ float g_opre[4*S_*DM_];     // 4 split-k partials for AV
__device__ float g_gmaxf;
__device__ float g_lnf[FEAT_];
__device__ float g_la[S_];
__device__ float g_e1t[S_*FEAT_];      // e1[ap][f] table
__device__ float g_gamt[S_*FEAT_];     // normalized gamma[ap][f] table

// ---------------- XLA-style f32 lgamma (Lanczos g=7), f32 dataflow via double ------
__device__ __forceinline__ float xla_lgammaf(float a) {
    const double C[8] = { 676.520368121885098567009190444019,
                        -1259.13921672240287047156078755283,
                          771.3234287776530788486528258894,
                         -176.61502916214059906584551354,
                           12.507343278686904814458936853,
                           -0.13857109526572011689554707,
                            9.984369578019570859563e-6,
                            1.50563273514931155834e-7 };
    float z = a - 1.0f;
    float x = 1.0f;
    #pragma unroll
    for (int k = 0; k < 8; k++) {
        float ck    = (float)C[k];
        float denom = (float)((double)z + (double)(k + 1));
        float term  = (float)((double)ck / (double)denom);
        x = (float)((double)x + (double)term);
    }
    float t     = (float)(7.5 + (double)z);
    float zq    = (float)((double)z / 7.5);
    float l1p   = (float)log1p((double)zq);
    float log_t = (float)((double)((float)2.0149030205422647) + (double)l1p);
    float tol   = (float)((double)t / (double)log_t);
    float zp    = (float)((double)z + 0.5);
    float inner = (float)((double)zp - (double)tol);
    float prod  = (float)((double)inner * (double)log_t);
    float res   = (float)((double)((float)0.91893853320467274178) + (double)prod);
    float lx    = (float)log((double)x);
    return (float)((double)res + (double)lx);
}

__device__ __forceinline__ float gamma_prob(int ap, int f) {
    if (ap <= 0) return 0.0f;
    float mean = 16.0f * (float)(f + 1);
    float cdiv = mean / 8.0f;
    float conc = cdiv * cdiv;
    float rate = mean / 64.0f;
    float cm1  = conc - 1.0f;
    float apf  = (float)ap;
    float lu1  = (float)((double)cm1 * (double)g_la[ap]);
    float lu2  = (float)((double)rate * (double)apf);
    float lu   = (float)((double)lu1 - (double)lu2);
    float arg  = (float)((double)lu - (double)g_lnf[f]);
    return (float)exp((double)arg);
}

// merged constants + analytic grid max (single block; all deps block-local)
__global__ void pe_init_kernel() {
    int tid = threadIdx.x;                     // 1024 threads
    for (int i = tid; i < S_; i += 1024)
        g_la[i] = (i > 0) ? (float)log((double)i) : 0.0f;
    if (tid < FEAT_) {
        float mean = 16.0f * (float)(tid + 1);
        float cdiv = mean / 8.0f;
        float conc = cdiv * cdiv;
        float rate = mean / 64.0f;
        float lg   = xla_lgammaf(conc);
        float lr   = (float)log((double)rate);
        float t2   = (float)((double)conc * (double)lr);
        g_lnf[tid] = (float)((double)lg - (double)t2);
    }
    __syncthreads();
    __shared__ float red[128];
    if (tid < 128) {
        float mean = 16.0f * (float)(tid + 1);
        int mode = (int)floor((double)mean - 64.0 / (double)mean);
        float best = 0.0f;
        #pragma unroll
        for (int d = -2; d <= 2; d++) {
            int ap = mode + d;
            if (ap < 1) ap = 1;
            if (ap > S_ - 1) ap = S_ - 1;
            best = fmaxf(best, gamma_prob(ap, tid));
        }
        red[tid] = best;
    }
    __syncthreads();
    for (int off = 64; off > 0; off >>= 1) {
        if (tid < off) red[tid] = fmaxf(red[tid], red[tid + off]);
        __syncthreads();
    }
    if (tid == 0) g_gmaxf = red[0];
}

__global__ void pe_table_kernel() {
    int idx = blockIdx.x * blockDim.x + threadIdx.x;
    int ap = idx >> 7, f = idx & 127;
    float apos = (float)ap;
    float step = (float)(8.0 / 127.0);
    float ex   = (float)(3.0 + (double)((float)((double)step * (double)f)));
    float hl   = (float)exp2((double)ex);
    float c    = (float)((double)(-(float)0.6931471805599453) / (double)hl);
    float arg  = (float)((double)c * (double)apos);
    g_e1t[idx] = (float)exp((double)arg);
    float prob = gamma_prob(ap, f);
    g_gamt[idx] = (float)((double)prob / (double)g_gmaxf);
}

__global__ void pe_fill_kernel() {
    int idx = blockIdx.x * blockDim.x + threadIdx.x;
    if (idx >= J_ * FEAT_) return;
    int p = idx / FEAT_, f = idx % FEAT_;
    int pos = p - (S_ - 1);
    int ap  = (pos < 0) ? -pos : pos;
    float apos = (float)ap;
    float sgn  = (pos > 0) ? 1.0f : (pos < 0 ? -1.0f : 0.0f);
    float e1   = g_e1t[(ap << 7) + f];
    float gam  = g_gamt[(ap << 7) + f];
    float cw   = exp2f((float)(f + 1)) - 1.0f;
    float cm   = (cw > apos) ? 1.0f : 0.0f;
    float* row = g_pe + (size_t)p * DM_;
    row[0   + f] = e1;
    row[128 + f] = e1 * sgn;
    row[256 + f] = cm;
    row[384 + f] = cm * sgn;
    row[512 + f] = gam;
    row[640 + f] = gam * sgn;
}

// ======== merged projections + fused bias epilogue: grid (12, 32, 4), 128 thr ======
// z 0..2: q/k/v (y<16); z==3: g_pe @ w_rk -> g_rk (y<32).
// z==1 also emits g_bw = r_w . kh rows; z==3 also emits g_br = r_r . rk rows.
__global__ __launch_bounds__(128) void proj_all_kernel(
    const float* __restrict__ q, const float* __restrict__ k, const float* __restrict__ v,
    const float* __restrict__ wq, const float* __restrict__ wk, const float* __restrict__ wv,
    const float* __restrict__ w_rk,
    const float* __restrict__ r_w, const float* __restrict__ r_r)
{
    int z = blockIdx.z;
    if (z < 3 && blockIdx.y >= 16) return;
    const float* A = (z == 0) ? q : (z == 1) ? k : (z == 2) ? v : (const float*)g_pe;
    const float* W = (z == 0) ? wq : (z == 1) ? wk : (z == 2) ? wv : w_rk;
    float* dst = (z == 0) ? g_qh : (z == 1) ? g_kh : (z == 2) ? g_vh : g_rk;
    float scale = (z == 0) ? 0.125f : 1.0f;
    int M = (z == 3) ? J_ : S_;
    __shared__ float AsT[2][16 * 132];
    __shared__ float Ws[2][16 * 68];
    int r0 = blockIdx.y * 128, c0 = blockIdx.x * 64;
    int h  = c0 >> 6;
    int tid = threadIdx.x, tx = tid & 7, ty = tid >> 3;
    u64 acc[8][4];
    #pragma unroll
    for (int i = 0; i < 8; i++)
        #pragma unroll
        for (int j = 0; j < 4; j++) acc[i][j] = 0ull;
    int vo = 8 * tx + ((tx >= 4) ? 4 : 0);

    int la_r[4], la_c4[4];
    #pragma unroll
    for (int it = 0; it < 4; it++) { int lin = tid + it * 128; la_r[it] = lin >> 2; la_c4[it] = lin & 3; }
    int lw_kx[2], lw_c4[2];
    #pragma unroll
    for (int it = 0; it < 2; it++) { int lin = tid + it * 128; lw_kx[it] = lin >> 4; lw_c4[it] = lin & 15; }

    float4 ra[4], rw[2];
    #pragma unroll
    for (int it = 0; it < 4; it++) {
        ra[it] = make_float4(0.f, 0.f, 0.f, 0.f);
        if (r0 + la_r[it] < M)
            ra[it] = *(const float4*)(A + (size_t)(r0 + la_r[it]) * DM_ + 4 * la_c4[it]);
    }
    #pragma unroll
    for (int it = 0; it < 2; it++)
        rw[it] = *(const float4*)(W + (size_t)lw_kx[it] * DM_ + c0 + 4 * lw_c4[it]);

    int buf = 0;
    for (int kki = 0; kki < 48; kki++) {
        #pragma unroll
        for (int it = 0; it < 4; it++) {
            float4 val = ra[it]; int r = la_r[it], c4 = la_c4[it];
            AsT[buf][(4 * c4 + 0) * 132 + r] = val.x;
            AsT[buf][(4 * c4 + 1) * 132 + r] = val.y;
            AsT[buf][(4 * c4 + 2) * 132 + r] = val.z;
            AsT[buf][(4 * c4 + 3) * 132 + r] = val.w;
        }
        #pragma unroll
        for (int it = 0; it < 2; it++) {
            int c4 = lw_c4[it], dd = 4 * c4 + ((c4 >= 8) ? 4 : 0);
            *(float4*)(&Ws[buf][lw_kx[it] * 68 + dd]) = rw[it];
        }
        __syncthreads();

        if (kki < 47) {
            int kk = (kki + 1) * 16;
            #pragma unroll
            for (int it = 0; it < 4; it++) {
                ra[it] = make_float4(0.f, 0.f, 0.f, 0.f);
                if (r0 + la_r[it] < M)
                    ra[it] = *(const float4*)(A + (size_t)(r0 + la_r[it]) * DM_ + kk + 4 * la_c4[it]);
            }
            #pragma unroll
            for (int it = 0; it < 2; it++)
                rw[it] = *(const float4*)(W + (size_t)(kk + lw_kx[it]) * DM_ + c0 + 4 * lw_c4[it]);
        }

        #pragma unroll 4
        for (int kx = 0; kx < 16; kx++) {
            float4 aa = *(const float4*)(&AsT[buf][kx * 132 + 8 * ty]);
            float4 ab = *(const float4*)(&AsT[buf][kx * 132 + 8 * ty + 4]);
            float4 wa = *(const float4*)(&Ws[buf][kx * 68 + vo]);
            float4 wb = *(const float4*)(&Ws[buf][kx * 68 + vo + 4]);
            u64 ap[8] = { pack2(aa.x, aa.x), pack2(aa.y, aa.y), pack2(aa.z, aa.z), pack2(aa.w, aa.w),
                          pack2(ab.x, ab.x), pack2(ab.y, ab.y), pack2(ab.z, ab.z), pack2(ab.w, ab.w) };
            u64 wp[4] = { pack2(wa.x, wa.y), pack2(wa.z, wa.w), pack2(wb.x, wb.y), pack2(wb.z, wb.w) };
            #pragma unroll
            for (int i = 0; i < 8; i++)
                #pragma unroll
                for (int j = 0; j < 4; j++) fma2(acc[i][j], ap[i], wp[j]);
        }
        buf ^= 1;
    }

    // fused bias setup (z==1: bw from kh with r_w; z==3: br from rk with r_r)
    bool bias_mode = (z == 1) || (z == 3);
    float rvv[8] = {0.f, 0.f, 0.f, 0.f, 0.f, 0.f, 0.f, 0.f};
    float* bout = (z == 1) ? g_bw : g_br;
    if (bias_mode) {
        const float* rv = (z == 1) ? r_w : r_r;
        *(float4*)rvv       = *(const float4*)(rv + h * DK_ + 8 * tx);
        *(float4*)(rvv + 4) = *(const float4*)(rv + h * DK_ + 8 * tx + 4);
    }

    #pragma unroll
    for (int i = 0; i < 8; i++) {
        int r = r0 + 8 * ty + i;
        float ov[8];
        #pragma unroll
        for (int j = 0; j < 4; j++) unpack2(acc[i][j], ov[2 * j], ov[2 * j + 1]);
        // bias partial + convergent 8-lane reduce (executed by all lanes, write guarded)
        float bsum = 0.0f;
        if (bias_mode) {
            #pragma unroll
            for (int j = 0; j < 8; j++) bsum += rvv[j] * ov[j];
            bsum += __shfl_xor_sync(0xffffffffu, bsum, 1);
            bsum += __shfl_xor_sync(0xffffffffu, bsum, 2);
            bsum += __shfl_xor_sync(0xffffffffu, bsum, 4);
        }
        if (r < M) {
            float4 o0 = make_float4(ov[0] * scale, ov[1] * scale, ov[2] * scale, ov[3] * scale);
            float4 o1 = make_float4(ov[4] * scale, ov[5] * scale, ov[6] * scale, ov[7] * scale);
            float* dp = dst + ((size_t)h * M + r) * DK_ + 8 * tx;
            *(float4*)dp = o0;
            *(float4*)(dp + 4) = o1;
            if (bias_mode && tx == 0) bout[h * M + r] = bsum;
        }
    }
}

// ======== output GEMM, double-buffered: pre-combined g_opre[2048,768] @ W + bias ===
__global__ __launch_bounds__(128) void gemm_bias_kernel(
    const float* __restrict__ W, const float* __restrict__ bias, float* __restrict__ dst)
{
    __shared__ float AsT[2][16 * 132];
    __shared__ float Ws[2][16 * 68];
    int r0 = blockIdx.y * 128, c0 = blockIdx.x * 64;
    int tid = threadIdx.x, tx = tid & 7, ty = tid >> 3;
    u64 acc[8][4];
    #pragma unroll
    for (int i = 0; i < 8; i++)
        #pragma unroll
        for (int j = 0; j < 4; j++) acc[i][j] = 0ull;
    int vo = 8 * tx + ((tx >= 4) ? 4 : 0);

    int la_r[4], la_c4[4];
    #pragma unroll
    for (int it = 0; it < 4; it++) { int lin = tid + it * 128; la_r[it] = lin >> 2; la_c4[it] = lin & 3; }
    int lw_kx[2], lw_c4[2];
    #pragma unroll
    for (int it = 0; it < 2; it++) { int lin = tid + it * 128; lw_kx[it] = lin >> 4; lw_c4[it] = lin & 15; }

    float4 ra[4], rw[2];
    #pragma unroll
    for (int it = 0; it < 4; it++)
        ra[it] = *(const float4*)(g_opre + (size_t)(r0 + la_r[it]) * DM_ + 4 * la_c4[it]);
    #pragma unroll
    for (int it = 0; it < 2; it++)
        rw[it] = *(const float4*)(W + (size_t)lw_kx[it] * DM_ + c0 + 4 * lw_c4[it]);

    int buf = 0;
    for (int kki = 0; kki < 48; kki++) {
        #pragma unroll
        for (int it = 0; it < 4; it++) {
            float4 val = ra[it]; int r = la_r[it], c4 = la_c4[it];
            AsT[buf][(4 * c4 + 0) * 132 + r] = val.x;
            AsT[buf][(4 * c4 + 1) * 132 + r] = val.y;
            AsT[buf][(4 * c4 + 2) * 132 + r] = val.z;
            AsT[buf][(4 * c4 + 3) * 132 + r] = val.w;
        }
        #pragma unroll
        for (int it = 0; it < 2; it++) {
            int c4 = lw_c4[it], dd = 4 * c4 + ((c4 >= 8) ? 4 : 0);
            *(float4*)(&Ws[buf][lw_kx[it] * 68 + dd]) = rw[it];
        }
        __syncthreads();

        if (kki < 47) {
            int kk = (kki + 1) * 16;
            #pragma unroll
            for (int it = 0; it < 4; it++)
                ra[it] = *(const float4*)(g_opre + (size_t)(r0 + la_r[it]) * DM_ + kk + 4 * la_c4[it]);
            #pragma unroll
            for (int it = 0; it < 2; it++)
                rw[it] = *(const float4*)(W + (size_t)(kk + lw_kx[it]) * DM_ + c0 + 4 * lw_c4[it]);
        }

        #pragma unroll 4
        for (int kx = 0; kx < 16; kx++) {
            float4 aa = *(const float4*)(&AsT[buf][kx * 132 + 8 * ty]);
            float4 ab = *(const float4*)(&AsT[buf][kx * 132 + 8 * ty + 4]);
            float4 wa = *(const float4*)(&Ws[buf][kx * 68 + vo]);
            float4 wb = *(const float4*)(&Ws[buf][kx * 68 + vo + 4]);
            u64 ap[8] = { pack2(aa.x, aa.x), pack2(aa.y, aa.y), pack2(aa.z, aa.z), pack2(aa.w, aa.w),
                          pack2(ab.x, ab.x), pack2(ab.y, ab.y), pack2(ab.z, ab.z), pack2(ab.w, ab.w) };
            u64 wp[4] = { pack2(wa.x, wa.y), pack2(wa.z, wa.w), pack2(wb.x, wb.y), pack2(wb.z, wb.w) };
            #pragma unroll
            for (int i = 0; i < 8; i++)
                #pragma unroll
                for (int j = 0; j < 4; j++) fma2(acc[i][j], ap[i], wp[j]);
        }
        buf ^= 1;
    }

    float4 b0 = *(const float4*)(bias + c0 + 8 * tx);
    float4 b1 = *(const float4*)(bias + c0 + 8 * tx + 4);
    #pragma unroll
    for (int i = 0; i < 8; i++) {
        int r = r0 + 8 * ty + i;
        float ov[8];
        #pragma unroll
        for (int j = 0; j < 4; j++) unpack2(acc[i][j], ov[2 * j], ov[2 * j + 1]);
        float4 o0 = make_float4(ov[0] + b0.x, ov[1] + b0.y, ov[2] + b0.z, ov[3] + b0.w);
        float4 o1 = make_float4(ov[4] + b1.x, ov[5] + b1.y, ov[6] + b1.z, ov[7] + b1.w);
        float* dp = dst + (size_t)r * DM_ + c0 + 8 * tx;
        *(float4*)dp = o0;
        *(float4*)(dp + 4) = o1;
    }
}

// ======== fused logits (R6 128x128 design, best measured) ==========================
__global__ __launch_bounds__(256) void logits_kernel(float* __restrict__ attn_arg)
{
    __shared__ float qsT[16 * 132];
    __shared__ float ksT[16 * 132];
    __shared__ float rs [16 * 256];
    __shared__ float bwS[128];
    __shared__ float brS[256];
    float* attn = attn_arg ? attn_arg : g_attn;
    int h = blockIdx.z, t0 = blockIdx.x * 128, s0 = blockIdx.y * 128;
    int tid = threadIdx.x, tx = tid & 15, ty = tid >> 4;

    const float* qb = g_qh + ((size_t)h * S_ + s0) * DK_;
    const float* kb = g_kh + ((size_t)h * S_ + t0) * DK_;
    int jbase = t0 - s0 + 1920;
    const float* rb = g_rk + ((size_t)h * J_ + jbase) * DK_;

    if (tid < 128) bwS[tid] = g_bw[h * S_ + t0 + tid];
    if (tid < 255) brS[tid] = g_br[h * J_ + jbase + tid];

    u64 acc[8][4];
    #pragma unroll
    for (int i = 0; i < 8; i++)
        #pragma unroll
        for (int j = 0; j < 4; j++) acc[i][j] = 0ull;

    int rb0 = 8 * (tx - ty) + 120;

    for (int phase = 0; phase < 4; phase++) {
        int dbase = phase * 16;
        __syncthreads();
        #pragma unroll
        for (int it = 0; it < 4; it++) {
            int lin = tid + it * 256;
            int m = lin >> 9;
            int l2 = lin & 511;
            int r = l2 >> 2, c4 = l2 & 3;
            const float* src = (m ? kb : qb) + (size_t)r * DK_ + dbase + 4 * c4;
            float4 val = *(const float4*)src;
            float* dstm = m ? ksT : qsT;
            dstm[(4 * c4 + 0) * 132 + r] = val.x;
            dstm[(4 * c4 + 1) * 132 + r] = val.y;
            dstm[(4 * c4 + 2) * 132 + r] = val.z;
            dstm[(4 * c4 + 3) * 132 + r] = val.w;
        }
        #pragma unroll
        for (int it = 0; it < 4; it++) {
            int lin = tid + it * 256;
            if (lin < 1020) {
                int jl = lin >> 2, c4 = lin & 3;
                float4 val = *(const float4*)(rb + (size_t)jl * DK_ + dbase + 4 * c4);
                rs[(4 * c4 + 0) * 256 + jl] = val.x;
                rs[(4 * c4 + 1) * 256 + jl] = val.y;
                rs[(4 * c4 + 2) * 256 + jl] = val.z;
                rs[(4 * c4 + 3) * 256 + jl] = val.w;
            }
        }
        __syncthreads();

        #pragma unroll 2
        for (int dl = 0; dl < 16; dl++) {
            float4 qa = *(const float4*)(qsT + dl * 132 + 8 * ty);
            float4 qb4 = *(const float4*)(qsT + dl * 132 + 8 * ty + 4);
            float4 ka = *(const float4*)(ksT + dl * 132 + 8 * tx);
            float4 kb4 = *(const float4*)(ksT + dl * 132 + 8 * tx + 4);
            const float* rp = rs + dl * 256 + rb0;
            float4 r0 = *(const float4*)(rp);
            float4 r1 = *(const float4*)(rp + 4);
            float4 r2 = *(const float4*)(rp + 8);
            float4 r3 = *(const float4*)(rp + 12);
            float rw[16] = { r0.x, r0.y, r0.z, r0.w, r1.x, r1.y, r1.z, r1.w,
                             r2.x, r2.y, r2.z, r2.w, r3.x, r3.y, r3.z, r3.w };
            u64 qq[8] = { pack2(qa.x, qa.x), pack2(qa.y, qa.y), pack2(qa.z, qa.z), pack2(qa.w, qa.w),
                          pack2(qb4.x, qb4.x), pack2(qb4.y, qb4.y), pack2(qb4.z, qb4.z), pack2(qb4.w, qb4.w) };
            u64 kp[4] = { pack2(ka.x, ka.y), pack2(ka.z, ka.w), pack2(kb4.x, kb4.y), pack2(kb4.z, kb4.w) };
            u64 E[7], O[7];
            #pragma unroll
            for (int vv = 0; vv < 7; vv++) {
                E[vv] = pack2(rw[2 * vv], rw[2 * vv + 1]);
                O[vv] = pack2(rw[2 * vv + 1], rw[2 * vv + 2]);
            }
            #pragma unroll
            for (int i = 0; i < 8; i++) {
                int eb = (7 - i) >> 1;
                #pragma unroll
                for (int j = 0; j < 4; j++) {
                    fma2(acc[i][j], qq[i], kp[j]);
                    fma2(acc[i][j], qq[i], (i & 1) ? E[j + eb] : O[j + eb]);
                }
            }
        }
    }

    #pragma unroll
    for (int i = 0; i < 8; i++) {
        int s_loc = 8 * ty + i;
        int s = s0 + s_loc;
        float ov[8];
        #pragma unroll
        for (int j = 0; j < 4; j++) unpack2(acc[i][j], ov[2 * j], ov[2 * j + 1]);
        #pragma unroll
        for (int jj = 0; jj < 8; jj++) {
            int tl = 8 * tx + jj;
            ov[jj] += bwS[tl] + brS[tl - s_loc + 127];
        }
        float* dp = attn + ((size_t)h * S_ + s) * S_ + t0 + 8 * tx;
        *(float4*)dp       = make_float4(ov[0], ov[1], ov[2], ov[3]);
        *(float4*)(dp + 4) = make_float4(ov[4], ov[5], ov[6], ov[7]);
    }
}

// ======== softmax: hybrid MUFU + f32x2-poly exp; REVERSED row order for L2 reuse ===
__device__ __forceinline__ u64 exp2_pair(float ylo, float yhi) {
    const float MAG = 12582912.0f;
    u64 y2 = pack2(ylo, yhi);
    u64 mag2 = pack2(MAG, MAG);
    u64 t2; asm("add.rn.f32x2 %0, %1, %2;" : "=l"(t2) : "l"(y2), "l"(mag2));
    float tlo, thi; unpack2(t2, tlo, thi);
    int nlo = __float_as_int(tlo) - 0x4B400000;
    int nhi = __float_as_int(thi) - 0x4B400000;
    u64 negone = pack2(-1.0f, -1.0f);
    u64 u2 = fma2n(mag2, negone, t2);
    u64 f2 = fma2n(u2, negone, y2);
    u64 p  = pack2(1.3333558146428443e-3f, 1.3333558146428443e-3f);
    p = fma2n(p, f2, pack2(9.618129107628477e-3f, 9.618129107628477e-3f));
    p = fma2n(p, f2, pack2(5.550410866482158e-2f, 5.550410866482158e-2f));
    p = fma2n(p, f2, pack2(2.402265069591007e-1f, 2.402265069591007e-1f));
    p = fma2n(p, f2, pack2(6.931471805599453e-1f, 6.931471805599453e-1f));
    p = fma2n(p, f2, pack2(1.0f, 1.0f));
    float plo, phi; unpack2(p, plo, phi);
    int rlo = __float_as_int(plo) + (nlo << 23);
    int rhi = __float_as_int(phi) + (nhi << 23);
    return pack2(__int_as_float(rlo), __int_as_float(rhi));
}

__global__ __launch_bounds__(256) void softmax_kernel(float* __restrict__ attn_arg)
{
    float* attn = attn_arg ? attn_arg : g_attn;
    size_t row = (size_t)(H_ * S_ - 1) - blockIdx.x;   // reversed: hit logits' L2 tail
    float* x = attn + row * S_;
    int tid = threadIdx.x;
    float4 a = *(const float4*)(x + 8 * tid);
    float4 b = *(const float4*)(x + 8 * tid + 4);
    float m = fmaxf(fmaxf(fmaxf(a.x, a.y), fmaxf(a.z, a.w)),
                    fmaxf(fmaxf(b.x, b.y), fmaxf(b.z, b.w)));
    __shared__ float red[8];
    #pragma unroll
    for (int off = 16; off; off >>= 1) m = fmaxf(m, __shfl_xor_sync(0xffffffffu, m, off));
    if ((tid & 31) == 0) red[tid >> 5] = m;
    __syncthreads();
    float mm = red[0];
    #pragma unroll
    for (int j = 1; j < 8; j++) mm = fmaxf(mm, red[j]);

    const float L2E = 1.4426950408889634f;
    float nm = -mm * L2E;
    float y0 = fmaf(a.x, L2E, nm), y1 = fmaf(a.y, L2E, nm);
    float y2 = fmaf(a.z, L2E, nm), y3 = fmaf(a.w, L2E, nm);
    float y4 = fmaf(b.x, L2E, nm), y5 = fmaf(b.y, L2E, nm);
    float y6 = fmaf(b.z, L2E, nm), y7 = fmaf(b.w, L2E, nm);

    float e0, e1, e2, e3;
    asm("ex2.approx.f32 %0, %1;" : "=f"(e0) : "f"(y0));
    asm("ex2.approx.f32 %0, %1;" : "=f"(e1) : "f"(y1));
    asm("ex2.approx.f32 %0, %1;" : "=f"(e2) : "f"(y2));
    asm("ex2.approx.f32 %0, %1;" : "=f"(e3) : "f"(y3));
    u64 r45 = exp2_pair(fmaxf(y4, -125.0f), fmaxf(y5, -125.0f));
    u64 r67 = exp2_pair(fmaxf(y6, -125.0f), fmaxf(y7, -125.0f));
    float e4, e5, e6, e7;
    unpack2(r45, e4, e5);
    unpack2(r67, e6, e7);

    float sum = ((e0 + e1) + (e2 + e3)) + ((e4 + e5) + (e6 + e7));
    #pragma unroll
    for (int off = 16; off; off >>= 1) sum += __shfl_xor_sync(0xffffffffu, sum, off);
    __syncthreads();
    if ((tid & 31) == 0) red[tid >> 5] = sum;
    __syncthreads();
    float ss = red[0];
    #pragma unroll
    for (int j = 1; j < 8; j++) ss += red[j];
    float inv = 1.0f / ss;

    *(float4*)(x + 8 * tid)     = make_float4(e0 * inv, e1 * inv, e2 * inv, e3 * inv);
    *(float4*)(x + 8 * tid + 4) = make_float4(e4 * inv, e5 * inv, e6 * inv, e7 * inv);
}

// ======== attn @ V split-k, double-buffered: grid (16, 12, 4) ======================
__global__ __launch_bounds__(128) void av_kernel(const float* __restrict__ attn_arg)
{
    const float* attn = attn_arg ? attn_arg : (const float*)g_attn;
    __shared__ float AsT[2][16 * 132];
    __shared__ float Vs[2][16 * 68];
    int s0 = blockIdx.x * 128, h = blockIdx.y, z = blockIdx.z;
    int tid = threadIdx.x, tx = tid & 7, ty = tid >> 3;
    const float* ab = attn + ((size_t)h * S_ + s0) * S_;
    const float* vb = g_vh + (size_t)h * S_ * DK_;
    u64 acc[8][4];
    #pragma unroll
    for (int i = 0; i < 8; i++)
        #pragma unroll
        for (int j = 0; j < 4; j++) acc[i][j] = 0ull;
    int vo = 8 * tx + ((tx >= 4) ? 4 : 0);

    int la_s[4], la_c4[4];
    #pragma unroll
    for (int it = 0; it < 4; it++) { int lin = tid + it * 128; la_s[it] = lin >> 2; la_c4[it] = lin & 3; }
    int lv_kx[2], lv_c4[2];
    #pragma unroll
    for (int it = 0; it < 2; it++) { int lin = tid + it * 128; lv_kx[it] = lin >> 4; lv_c4[it] = lin & 15; }

    int k0 = z * 512;
    float4 ra[4], rv[2];
    #pragma unroll
    for (int it = 0; it < 4; it++)
        ra[it] = *(const float4*)(ab + (size_t)la_s[it] * S_ + k0 + 4 * la_c4[it]);
    #pragma unroll
    for (int it = 0; it < 2; it++)
        rv[it] = *(const float4*)(vb + (size_t)(k0 + lv_kx[it]) * DK_ + 4 * lv_c4[it]);

    int buf = 0;
    for (int kki = 0; kki < 32; kki++) {
        #pragma unroll
        for (int it = 0; it < 4; it++) {
            float4 val = ra[it]; int s = la_s[it], c4 = la_c4[it];
            AsT[buf][(4 * c4 + 0) * 132 + s] = val.x;
            AsT[buf][(4 * c4 + 1) * 132 + s] = val.y;
            AsT[buf][(4 * c4 + 2) * 132 + s] = val.z;
            AsT[buf][(4 * c4 + 3) * 132 + s] = val.w;
        }
        #pragma unroll
        for (int it = 0; it < 2; it++) {
            int c4 = lv_c4[it], dd = 4 * c4 + ((c4 >= 8) ? 4 : 0);
            *(float4*)(&Vs[buf][lv_kx[it] * 68 + dd]) = rv[it];
        }
        __syncthreads();

        if (kki < 31) {
            int kk = k0 + (kki + 1) * 16;
            #pragma unroll
            for (int it = 0; it < 4; it++)
                ra[it] = *(const float4*)(ab + (size_t)la_s[it] * S_ + kk + 4 * la_c4[it]);
            #pragma unroll
            for (int it = 0; it < 2; it++)
                rv[it] = *(const float4*)(vb + (size_t)(kk + lv_kx[it]) * DK_ + 4 * lv_c4[it]);
        }

        #pragma unroll 4
        for (int kx = 0; kx < 16; kx++) {
            float4 aa = *(const float4*)(&AsT[buf][kx * 132 + 8 * ty]);
            float4 ab4 = *(const float4*)(&AsT[buf][kx * 132 + 8 * ty + 4]);
            float4 va = *(const float4*)(&Vs[buf][kx * 68 + vo]);
            float4 vb4 = *(const float4*)(&Vs[buf][kx * 68 + vo + 4]);
            u64 ap[8] = { pack2(aa.x, aa.x), pack2(aa.y, aa.y), pack2(aa.z, aa.z), pack2(aa.w, aa.w),
                          pack2(ab4.x, ab4.x), pack2(ab4.y, ab4.y), pack2(ab4.z, ab4.z), pack2(ab4.w, ab4.w) };
            u64 vp[4] = { pack2(va.x, va.y), pack2(va.z, va.w), pack2(vb4.x, vb4.y), pack2(vb4.z, vb4.w) };
            #pragma unroll
            for (int i = 0; i < 8; i++)
                #pragma unroll
                for (int j = 0; j < 4; j++) fma2(acc[i][j], ap[i], vp[j]);
        }
        buf ^= 1;
    }

    #pragma unroll
    for (int i = 0; i < 8; i++) {
        int s = s0 + 8 * ty + i;
        float ov[8];
        #pragma unroll
        for (int j = 0; j < 4; j++) unpack2(acc[i][j], ov[2 * j], ov[2 * j + 1]);
        float* dp = g_opre + ((size_t)z * S_ + s) * DM_ + h * DK_ + 8 * tx;
        *(float4*)dp       = make_float4(ov[0], ov[1], ov[2], ov[3]);
        *(float4*)(dp + 4) = make_float4(ov[4], ov[5], ov[6], ov[7]);
    }
}

// ---------------- combine 4 AV partials into partial 0 -----------------------------
__global__ __launch_bounds__(256) void combine_kernel()
{
    size_t base = (size_t)blockIdx.x * blockDim.x * 2 + threadIdx.x;
    const size_t N = (size_t)S_ * DM_;
    #pragma unroll
    for (int rep = 0; rep < 2; rep++) {
        size_t idx = base + (size_t)rep * blockDim.x;
        float4 r0 = ((float4*)g_opre)[idx];
        float4 r1 = ((float4*)(g_opre + N))[idx];
        float4 r2 = ((float4*)(g_opre + 2 * N))[idx];
        float4 r3 = ((float4*)(g_opre + 3 * N))[idx];
        r0.x = (r0.x + r1.x) + (r2.x + r3.x);
        r0.y = (r0.y + r1.y) + (r2.y + r3.y);
        r0.z = (r0.z + r1.z) + (r2.z + r3.z);
        r0.w = (r0.w + r1.w) + (r2.w + r3.w);
        ((float4*)g_opre)[idx] = r0;
    }
}

// ---------------- host launcher -----------------------------------------------------
extern "C" void kernel_launch(void* const* d_in, const int* in_sizes, int n_in,
                              void* d_out, int out_size)
{
    const int QKV = 1572864, WMAT = 589824, VEC = 768;
    const float *q, *k, *v, *wq, *wk, *wv, *w_rk, *r_w, *r_r, *w_out, *b_out;
    if (n_in >= 11 && in_sizes[0] == VEC && in_sizes[1] == QKV && in_sizes[5] == QKV
        && in_sizes[6] == WMAT) {
        b_out = (const float*)d_in[0];
        k     = (const float*)d_in[1];
        q     = (const float*)d_in[2];
        r_r   = (const float*)d_in[3];
        r_w   = (const float*)d_in[4];
        v     = (const float*)d_in[5];
        w_out = (const float*)d_in[6];
        w_rk  = (const float*)d_in[7];
        wk    = (const float*)d_in[8];
        wq    = (const float*)d_in[9];
        wv    = (const float*)d_in[10];
    } else {
        q     = (const float*)d_in[0];
        k     = (const float*)d_in[1];
        v     = (const float*)d_in[2];
        wq    = (const float*)d_in[3];
        wk    = (const float*)d_in[4];
        wv    = (const float*)d_in[5];
        w_rk  = (const float*)d_in[6];
        r_w   = (const float*)d_in[7];
        r_r   = (const float*)d_in[8];
        w_out = (const float*)d_in[9];
        b_out = (const float*)d_in[10];
    }

    const long long OUT_E  = (long long)S_ * DM_;
    const long long ATTN_E = (long long)H_ * S_ * S_;
    long long os = (long long)out_size;

    float* out_ptr  = (float*)d_out;
    float* attn_ptr = nullptr;
    bool need_out = true;

    if (os >= OUT_E + ATTN_E) {
        attn_ptr = (float*)d_out + OUT_E;
    } else if (os == ATTN_E) {
        attn_ptr = (float*)d_out;
        need_out = false;
    }

    pe_init_kernel<<<1, 1024>>>();
    pe_table_kernel<<<1024, 256>>>();
    pe_fill_kernel<<<2048, 256>>>();

    proj_all_kernel<<<dim3(12, 32, 4), 128>>>(q, k, v, wq, wk, wv, w_rk, r_w, r_r);

    logits_kernel<<<dim3(16, 16, 12), 256>>>(attn_ptr);

    softmax_kernel<<<H_ * S_, 256>>>(attn_ptr);

    if (need_out) {
        av_kernel<<<dim3(16, 12, 4), 128>>>(attn_ptr);
        combine_kernel<<<768, 256>>>();
        gemm_bias_kernel<<<dim3(12, 16), 128>>>(w_out, b_out, out_ptr);
    }
}

// round 16
// speedup vs baseline: 1.0295x; 1.0295x over previous
#include <cuda_runtime.h>
#include <math.h>

#define S_    2048
#define DM_   768
#define H_    12
#define DK_   64
#define FEAT_ 128
#define J_    4095   /* 2S-1 */

typedef unsigned long long u64;

__device__ __forceinline__ u64 pack2(float lo, float hi) {
    u64 r; asm("mov.b64 %0, {%1, %2};" : "=l"(r) : "f"(lo), "f"(hi)); return r;
}
__device__ __forceinline__ void unpack2(u64 v, float& lo, float& hi) {
    asm("mov.b64 {%0, %1}, %2;" : "=f"(lo), "=f"(hi) : "l"(v));
}
__device__ __forceinline__ void fma2(u64& d, u64 a, u64 b) {
    asm("fma.rn.f32x2 %0, %1, %2, %0;" : "+l"(d) : "l"(a), "l"(b));
}
__device__ __forceinline__ u64 fma2n(u64 a, u64 b, u64 c) {
    u64 d; asm("fma.rn.f32x2 %0, %1, %2, %3;" : "=l"(d) : "l"(a), "l"(b), "l"(c)); return d;
}
__device__ __forceinline__ float ex2a(float y) {
    float e; asm("ex2.approx.f32 %0, %1;" : "=f"(e) : "f"(y)); return e;
}

// ---------------- scratch (static device globals; referenced ONLY in device code) --
__device__ float g_qh[H_*S_*DK_];
__device__ float g_kh[H_*S_*DK_];
__device__ float g_vh[H_*S_*DK_];
__device__ float g_pe[J_*DM_];
__device__ float g_rk[H_*J_*DK_];
__device__ float g_bw[H_*S_];
__device__ float g_br[H_*J_];
__device__ float g_attn[H_*S_*S_];
__device__ float g_opre[4*S_*DM_];     // 4 split-k partials for AV
__device__ float2 g_part[H_*S_*16];    // per-(row, col-tile) softmax partials (m, sumexp)
__device__ float2 g_rowm[H_*S_];       // per-row (M*log2e, 1/sum)
__device__ float g_gmaxf;
__device__ float g_lnf[FEAT_];
__device__ float g_la[S_];
__device__ float g_e1t[S_*FEAT_];      // e1[ap][f] table
__device__ float g_gamt[S_*FEAT_];     // normalized gamma[ap][f] table

// ---------------- XLA-style f32 lgamma (Lanczos g=7), f32 dataflow via double ------
__device__ __forceinline__ float xla_lgammaf(float a) {
    const double C[8] = { 676.520368121885098567009190444019,
                        -1259.13921672240287047156078755283,
                          771.3234287776530788486528258894,
                         -176.61502916214059906584551354,
                           12.507343278686904814458936853,
                           -0.13857109526572011689554707,
                            9.984369578019570859563e-6,
                            1.50563273514931155834e-7 };
    float z = a - 1.0f;
    float x = 1.0f;
    #pragma unroll
    for (int k = 0; k < 8; k++) {
        float ck    = (float)C[k];
        float denom = (float)((double)z + (double)(k + 1));
        float term  = (float)((double)ck / (double)denom);
        x = (float)((double)x + (double)term);
    }
    float t     = (float)(7.5 + (double)z);
    float zq    = (float)((double)z / 7.5);
    float l1p   = (float)log1p((double)zq);
    float log_t = (float)((double)((float)2.0149030205422647) + (double)l1p);
    float tol   = (float)((double)t / (double)log_t);
    float zp    = (float)((double)z + 0.5);
    float inner = (float)((double)zp - (double)tol);
    float prod  = (float)((double)inner * (double)log_t);
    float res   = (float)((double)((float)0.91893853320467274178) + (double)prod);
    float lx    = (float)log((double)x);
    return (float)((double)res + (double)lx);
}

__global__ void pe_const_kernel() {
    int i = blockIdx.x * blockDim.x + threadIdx.x;
    if (i < S_) g_la[i] = (i > 0) ? (float)log((double)i) : 0.0f;
    if (i < FEAT_) {
        float mean = 16.0f * (float)(i + 1);
        float cdiv = mean / 8.0f;
        float conc = cdiv * cdiv;
        float rate = mean / 64.0f;
        float lg   = xla_lgammaf(conc);
        float lr   = (float)log((double)rate);
        float t2   = (float)((double)conc * (double)lr);
        g_lnf[i]   = (float)((double)lg - (double)t2);
    }
}

__device__ __forceinline__ float gamma_prob(int ap, int f) {
    if (ap <= 0) return 0.0f;
    float mean = 16.0f * (float)(f + 1);
    float cdiv = mean / 8.0f;
    float conc = cdiv * cdiv;
    float rate = mean / 64.0f;
    float cm1  = conc - 1.0f;
    float apf  = (float)ap;
    float lu1  = (float)((double)cm1 * (double)g_la[ap]);
    float lu2  = (float)((double)rate * (double)apf);
    float lu   = (float)((double)lu1 - (double)lu2);
    float arg  = (float)((double)lu - (double)g_lnf[f]);
    return (float)exp((double)arg);
}

__global__ void pe_gmax_kernel() {
    int f = threadIdx.x;
    float mean = 16.0f * (float)(f + 1);
    int mode = (int)floor((double)mean - 64.0 / (double)mean);
    float best = 0.0f;
    #pragma unroll
    for (int d = -2; d <= 2; d++) {
        int ap = mode + d;
        if (ap < 1) ap = 1;
        if (ap > S_ - 1) ap = S_ - 1;
        best = fmaxf(best, gamma_prob(ap, f));
    }
    __shared__ float red[128];
    red[f] = best;
    __syncthreads();
    for (int off = 64; off > 0; off >>= 1) {
        if (f < off) red[f] = fmaxf(red[f], red[f + off]);
        __syncthreads();
    }
    if (f == 0) g_gmaxf = red[0];
}

__global__ void pe_table_kernel() {
    int idx = blockIdx.x * blockDim.x + threadIdx.x;
    int ap = idx >> 7, f = idx & 127;
    float apos = (float)ap;
    float step = (float)(8.0 / 127.0);
    float ex   = (float)(3.0 + (double)((float)((double)step * (double)f)));
    float hl   = (float)exp2((double)ex);
    float c    = (float)((double)(-(float)0.6931471805599453) / (double)hl);
    float arg  = (float)((double)c * (double)apos);
    g_e1t[idx] = (float)exp((double)arg);
    float prob = gamma_prob(ap, f);
    g_gamt[idx] = (float)((double)prob / (double)g_gmaxf);
}

__global__ void pe_fill_kernel() {
    int idx = blockIdx.x * blockDim.x + threadIdx.x;
    if (idx >= J_ * FEAT_) return;
    int p = idx / FEAT_, f = idx % FEAT_;
    int pos = p - (S_ - 1);
    int ap  = (pos < 0) ? -pos : pos;
    float apos = (float)ap;
    float sgn  = (pos > 0) ? 1.0f : (pos < 0 ? -1.0f : 0.0f);
    float e1   = g_e1t[(ap << 7) + f];
    float gam  = g_gamt[(ap << 7) + f];
    float cw   = exp2f((float)(f + 1)) - 1.0f;
    float cm   = (cw > apos) ? 1.0f : 0.0f;
    float* row = g_pe + (size_t)p * DM_;
    row[0   + f] = e1;
    row[128 + f] = e1 * sgn;
    row[256 + f] = cm;
    row[384 + f] = cm * sgn;
    row[512 + f] = gam;
    row[640 + f] = gam * sgn;
}

// ======== merged projections, double-buffered: grid (12, 32, 4), 128 thr ===========
__global__ __launch_bounds__(128) void proj_all_kernel(
    const float* __restrict__ q, const float* __restrict__ k, const float* __restrict__ v,
    const float* __restrict__ wq, const float* __restrict__ wk, const float* __restrict__ wv,
    const float* __restrict__ w_rk)
{
    int z = blockIdx.z;
    if (z < 3 && blockIdx.y >= 16) return;
    const float* A = (z == 0) ? q : (z == 1) ? k : (z == 2) ? v : (const float*)g_pe;
    const float* W = (z == 0) ? wq : (z == 1) ? wk : (z == 2) ? wv : w_rk;
    float* dst = (z == 0) ? g_qh : (z == 1) ? g_kh : (z == 2) ? g_vh : g_rk;
    float scale = (z == 0) ? 0.125f : 1.0f;
    int M = (z == 3) ? J_ : S_;
    __shared__ float AsT[2][16 * 132];
    __shared__ float Ws[2][16 * 68];
    int r0 = blockIdx.y * 128, c0 = blockIdx.x * 64;
    int h  = c0 >> 6;
    int tid = threadIdx.x, tx = tid & 7, ty = tid >> 3;
    u64 acc[8][4];
    #pragma unroll
    for (int i = 0; i < 8; i++)
        #pragma unroll
        for (int j = 0; j < 4; j++) acc[i][j] = 0ull;
    int vo = 8 * tx + ((tx >= 4) ? 4 : 0);

    int la_r[4], la_c4[4];
    #pragma unroll
    for (int it = 0; it < 4; it++) { int lin = tid + it * 128; la_r[it] = lin >> 2; la_c4[it] = lin & 3; }
    int lw_kx[2], lw_c4[2];
    #pragma unroll
    for (int it = 0; it < 2; it++) { int lin = tid + it * 128; lw_kx[it] = lin >> 4; lw_c4[it] = lin & 15; }

    float4 ra[4], rw[2];
    #pragma unroll
    for (int it = 0; it < 4; it++) {
        ra[it] = make_float4(0.f, 0.f, 0.f, 0.f);
        if (r0 + la_r[it] < M)
            ra[it] = *(const float4*)(A + (size_t)(r0 + la_r[it]) * DM_ + 4 * la_c4[it]);
    }
    #pragma unroll
    for (int it = 0; it < 2; it++)
        rw[it] = *(const float4*)(W + (size_t)lw_kx[it] * DM_ + c0 + 4 * lw_c4[it]);

    int buf = 0;
    for (int kki = 0; kki < 48; kki++) {
        #pragma unroll
        for (int it = 0; it < 4; it++) {
            float4 val = ra[it]; int r = la_r[it], c4 = la_c4[it];
            AsT[buf][(4 * c4 + 0) * 132 + r] = val.x;
            AsT[buf][(4 * c4 + 1) * 132 + r] = val.y;
            AsT[buf][(4 * c4 + 2) * 132 + r] = val.z;
            AsT[buf][(4 * c4 + 3) * 132 + r] = val.w;
        }
        #pragma unroll
        for (int it = 0; it < 2; it++) {
            int c4 = lw_c4[it], dd = 4 * c4 + ((c4 >= 8) ? 4 : 0);
            *(float4*)(&Ws[buf][lw_kx[it] * 68 + dd]) = rw[it];
        }
        __syncthreads();

        if (kki < 47) {
            int kk = (kki + 1) * 16;
            #pragma unroll
            for (int it = 0; it < 4; it++) {
                ra[it] = make_float4(0.f, 0.f, 0.f, 0.f);
                if (r0 + la_r[it] < M)
                    ra[it] = *(const float4*)(A + (size_t)(r0 + la_r[it]) * DM_ + kk + 4 * la_c4[it]);
            }
            #pragma unroll
            for (int it = 0; it < 2; it++)
                rw[it] = *(const float4*)(W + (size_t)(kk + lw_kx[it]) * DM_ + c0 + 4 * lw_c4[it]);
        }

        #pragma unroll 4
        for (int kx = 0; kx < 16; kx++) {
            float4 aa = *(const float4*)(&AsT[buf][kx * 132 + 8 * ty]);
            float4 ab = *(const float4*)(&AsT[buf][kx * 132 + 8 * ty + 4]);
            float4 wa = *(const float4*)(&Ws[buf][kx * 68 + vo]);
            float4 wb = *(const float4*)(&Ws[buf][kx * 68 + vo + 4]);
            u64 ap[8] = { pack2(aa.x, aa.x), pack2(aa.y, aa.y), pack2(aa.z, aa.z), pack2(aa.w, aa.w),
                          pack2(ab.x, ab.x), pack2(ab.y, ab.y), pack2(ab.z, ab.z), pack2(ab.w, ab.w) };
            u64 wp[4] = { pack2(wa.x, wa.y), pack2(wa.z, wa.w), pack2(wb.x, wb.y), pack2(wb.z, wb.w) };
            #pragma unroll
            for (int i = 0; i < 8; i++)
                #pragma unroll
                for (int j = 0; j < 4; j++) fma2(acc[i][j], ap[i], wp[j]);
        }
        buf ^= 1;
    }

    #pragma unroll
    for (int i = 0; i < 8; i++) {
        int r = r0 + 8 * ty + i;
        if (r >= M) continue;
        float ov[8];
        #pragma unroll
        for (int j = 0; j < 4; j++) unpack2(acc[i][j], ov[2 * j], ov[2 * j + 1]);
        float4 o0 = make_float4(ov[0] * scale, ov[1] * scale, ov[2] * scale, ov[3] * scale);
        float4 o1 = make_float4(ov[4] * scale, ov[5] * scale, ov[6] * scale, ov[7] * scale);
        float* dp = dst + ((size_t)h * M + r) * DK_ + 8 * tx;
        *(float4*)dp = o0;
        *(float4*)(dp + 4) = o1;
    }
}

// ======== output GEMM, double-buffered: pre-combined g_opre[2048,768] @ W + bias ===
__global__ __launch_bounds__(128) void gemm_bias_kernel(
    const float* __restrict__ W, const float* __restrict__ bias, float* __restrict__ dst)
{
    __shared__ float AsT[2][16 * 132];
    __shared__ float Ws[2][16 * 68];
    int r0 = blockIdx.y * 128, c0 = blockIdx.x * 64;
    int tid = threadIdx.x, tx = tid & 7, ty = tid >> 3;
    u64 acc[8][4];
    #pragma unroll
    for (int i = 0; i < 8; i++)
        #pragma unroll
        for (int j = 0; j < 4; j++) acc[i][j] = 0ull;
    int vo = 8 * tx + ((tx >= 4) ? 4 : 0);

    int la_r[4], la_c4[4];
    #pragma unroll
    for (int it = 0; it < 4; it++) { int lin = tid + it * 128; la_r[it] = lin >> 2; la_c4[it] = lin & 3; }
    int lw_kx[2], lw_c4[2];
    #pragma unroll
    for (int it = 0; it < 2; it++) { int lin = tid + it * 128; lw_kx[it] = lin >> 4; lw_c4[it] = lin & 15; }

    float4 ra[4], rw[2];
    #pragma unroll
    for (int it = 0; it < 4; it++)
        ra[it] = *(const float4*)(g_opre + (size_t)(r0 + la_r[it]) * DM_ + 4 * la_c4[it]);
    #pragma unroll
    for (int it = 0; it < 2; it++)
        rw[it] = *(const float4*)(W + (size_t)lw_kx[it] * DM_ + c0 + 4 * lw_c4[it]);

    int buf = 0;
    for (int kki = 0; kki < 48; kki++) {
        #pragma unroll
        for (int it = 0; it < 4; it++) {
            float4 val = ra[it]; int r = la_r[it], c4 = la_c4[it];
            AsT[buf][(4 * c4 + 0) * 132 + r] = val.x;
            AsT[buf][(4 * c4 + 1) * 132 + r] = val.y;
            AsT[buf][(4 * c4 + 2) * 132 + r] = val.z;
            AsT[buf][(4 * c4 + 3) * 132 + r] = val.w;
        }
        #pragma unroll
        for (int it = 0; it < 2; it++) {
            int c4 = lw_c4[it], dd = 4 * c4 + ((c4 >= 8) ? 4 : 0);
            *(float4*)(&Ws[buf][lw_kx[it] * 68 + dd]) = rw[it];
        }
        __syncthreads();

        if (kki < 47) {
            int kk = (kki + 1) * 16;
            #pragma unroll
            for (int it = 0; it < 4; it++)
                ra[it] = *(const float4*)(g_opre + (size_t)(r0 + la_r[it]) * DM_ + kk + 4 * la_c4[it]);
            #pragma unroll
            for (int it = 0; it < 2; it++)
                rw[it] = *(const float4*)(W + (size_t)(kk + lw_kx[it]) * DM_ + c0 + 4 * lw_c4[it]);
        }

        #pragma unroll 4
        for (int kx = 0; kx < 16; kx++) {
            float4 aa = *(const float4*)(&AsT[buf][kx * 132 + 8 * ty]);
            float4 ab = *(const float4*)(&AsT[buf][kx * 132 + 8 * ty + 4]);
            float4 wa = *(const float4*)(&Ws[buf][kx * 68 + vo]);
            float4 wb = *(const float4*)(&Ws[buf][kx * 68 + vo + 4]);
            u64 ap[8] = { pack2(aa.x, aa.x), pack2(aa.y, aa.y), pack2(aa.z, aa.z), pack2(aa.w, aa.w),
                          pack2(ab.x, ab.x), pack2(ab.y, ab.y), pack2(ab.z, ab.z), pack2(ab.w, ab.w) };
            u64 wp[4] = { pack2(wa.x, wa.y), pack2(wa.z, wa.w), pack2(wb.x, wb.y), pack2(wb.z, wb.w) };
            #pragma unroll
            for (int i = 0; i < 8; i++)
                #pragma unroll
                for (int j = 0; j < 4; j++) fma2(acc[i][j], ap[i], wp[j]);
        }
        buf ^= 1;
    }

    float4 b0 = *(const float4*)(bias + c0 + 8 * tx);
    float4 b1 = *(const float4*)(bias + c0 + 8 * tx + 4);
    #pragma unroll
    for (int i = 0; i < 8; i++) {
        int r = r0 + 8 * ty + i;
        float ov[8];
        #pragma unroll
        for (int j = 0; j < 4; j++) unpack2(acc[i][j], ov[2 * j], ov[2 * j + 1]);
        float4 o0 = make_float4(ov[0] + b0.x, ov[1] + b0.y, ov[2] + b0.z, ov[3] + b0.w);
        float4 o1 = make_float4(ov[4] + b1.x, ov[5] + b1.y, ov[6] + b1.z, ov[7] + b1.w);
        float* dp = dst + (size_t)r * DM_ + c0 + 8 * tx;
        *(float4*)dp = o0;
        *(float4*)(dp + 4) = o1;
    }
}

// ---------------- bias vectors: warp-per-row, coalesced float2 + shuffle -----------
__global__ void bias_kernel(const float* __restrict__ r_w, const float* __restrict__ r_r)
{
    int gw = (blockIdx.x * blockDim.x + threadIdx.x) >> 5;
    int lane = threadIdx.x & 31;
    const int NB = H_ * S_;
    const int NR = H_ * J_;
    if (gw >= NB + NR) return;
    const float* rvec; const float* mat; float* out; int M; int li;
    if (gw < NB) { rvec = r_w; mat = g_kh; out = g_bw; M = S_; li = gw; }
    else         { rvec = r_r; mat = g_rk; out = g_br; M = J_; li = gw - NB; }
    int h = li / M, t = li % M;
    float2 rv = *(const float2*)(rvec + h * DK_ + 2 * lane);
    float2 mv = *(const float2*)(mat + ((size_t)h * M + t) * DK_ + 2 * lane);
    float s = rv.x * mv.x + rv.y * mv.y;
    #pragma unroll
    for (int off = 16; off; off >>= 1) s += __shfl_xor_sync(0xffffffffu, s, off);
    if (lane == 0) out[li] = s;
}

// ======== fused logits + per-tile softmax partials =================================
__global__ __launch_bounds__(256) void logits_kernel(float* __restrict__ attn_arg)
{
    __shared__ float qsT[16 * 132];
    __shared__ float ksT[16 * 132];
    __shared__ float rs [16 * 256];
    __shared__ float bwS[128];
    __shared__ float brS[256];
    float* attn = attn_arg ? attn_arg : g_attn;
    int h = blockIdx.z, t0 = blockIdx.x * 128, s0 = blockIdx.y * 128;
    int tid = threadIdx.x, tx = tid & 15, ty = tid >> 4;

    const float* qb = g_qh + ((size_t)h * S_ + s0) * DK_;
    const float* kb = g_kh + ((size_t)h * S_ + t0) * DK_;
    int jbase = t0 - s0 + 1920;
    const float* rb = g_rk + ((size_t)h * J_ + jbase) * DK_;

    if (tid < 128) bwS[tid] = g_bw[h * S_ + t0 + tid];
    if (tid < 255) brS[tid] = g_br[h * J_ + jbase + tid];

    u64 acc[8][4];
    #pragma unroll
    for (int i = 0; i < 8; i++)
        #pragma unroll
        for (int j = 0; j < 4; j++) acc[i][j] = 0ull;

    int rb0 = 8 * (tx - ty) + 120;

    for (int phase = 0; phase < 4; phase++) {
        int dbase = phase * 16;
        __syncthreads();
        #pragma unroll
        for (int it = 0; it < 4; it++) {
            int lin = tid + it * 256;
            int m = lin >> 9;
            int l2 = lin & 511;
            int r = l2 >> 2, c4 = l2 & 3;
            const float* src = (m ? kb : qb) + (size_t)r * DK_ + dbase + 4 * c4;
            float4 val = *(const float4*)src;
            float* dstm = m ? ksT : qsT;
            dstm[(4 * c4 + 0) * 132 + r] = val.x;
            dstm[(4 * c4 + 1) * 132 + r] = val.y;
            dstm[(4 * c4 + 2) * 132 + r] = val.z;
            dstm[(4 * c4 + 3) * 132 + r] = val.w;
        }
        #pragma unroll
        for (int it = 0; it < 4; it++) {
            int lin = tid + it * 256;
            if (lin < 1020) {
                int jl = lin >> 2, c4 = lin & 3;
                float4 val = *(const float4*)(rb + (size_t)jl * DK_ + dbase + 4 * c4);
                rs[(4 * c4 + 0) * 256 + jl] = val.x;
                rs[(4 * c4 + 1) * 256 + jl] = val.y;
                rs[(4 * c4 + 2) * 256 + jl] = val.z;
                rs[(4 * c4 + 3) * 256 + jl] = val.w;
            }
        }
        __syncthreads();

        #pragma unroll 2
        for (int dl = 0; dl < 16; dl++) {
            float4 qa = *(const float4*)(qsT + dl * 132 + 8 * ty);
            float4 qb4 = *(const float4*)(qsT + dl * 132 + 8 * ty + 4);
            float4 ka = *(const float4*)(ksT + dl * 132 + 8 * tx);
            float4 kb4 = *(const float4*)(ksT + dl * 132 + 8 * tx + 4);
            const float* rp = rs + dl * 256 + rb0;
            float4 r0 = *(const float4*)(rp);
            float4 r1 = *(const float4*)(rp + 4);
            float4 r2 = *(const float4*)(rp + 8);
            float4 r3 = *(const float4*)(rp + 12);
            float rw[16] = { r0.x, r0.y, r0.z, r0.w, r1.x, r1.y, r1.z, r1.w,
                             r2.x, r2.y, r2.z, r2.w, r3.x, r3.y, r3.z, r3.w };
            u64 qq[8] = { pack2(qa.x, qa.x), pack2(qa.y, qa.y), pack2(qa.z, qa.z), pack2(qa.w, qa.w),
                          pack2(qb4.x, qb4.x), pack2(qb4.y, qb4.y), pack2(qb4.z, qb4.z), pack2(qb4.w, qb4.w) };
            u64 kp[4] = { pack2(ka.x, ka.y), pack2(ka.z, ka.w), pack2(kb4.x, kb4.y), pack2(kb4.z, kb4.w) };
            u64 E[7], O[7];
            #pragma unroll
            for (int vv = 0; vv < 7; vv++) {
                E[vv] = pack2(rw[2 * vv], rw[2 * vv + 1]);
                O[vv] = pack2(rw[2 * vv + 1], rw[2 * vv + 2]);
            }
            #pragma unroll
            for (int i = 0; i < 8; i++) {
                int eb = (7 - i) >> 1;
                #pragma unroll
                for (int j = 0; j < 4; j++) {
                    fma2(acc[i][j], qq[i], kp[j]);
                    fma2(acc[i][j], qq[i], (i & 1) ? E[j + eb] : O[j + eb]);
                }
            }
        }
    }

    const float L2E = 1.4426950408889634f;
    #pragma unroll
    for (int i = 0; i < 8; i++) {
        int s_loc = 8 * ty + i;
        int s = s0 + s_loc;
        float ov[8];
        #pragma unroll
        for (int j = 0; j < 4; j++) unpack2(acc[i][j], ov[2 * j], ov[2 * j + 1]);
        #pragma unroll
        for (int jj = 0; jj < 8; jj++) {
            int tl = 8 * tx + jj;
            ov[jj] += bwS[tl] + brS[tl - s_loc + 127];
        }
        // per-(row, tile) softmax partials: max + sumexp over this 128-col tile
        float tm = ov[0];
        #pragma unroll
        for (int jj = 1; jj < 8; jj++) tm = fmaxf(tm, ov[jj]);
        tm = fmaxf(tm, __shfl_xor_sync(0xffffffffu, tm, 1));
        tm = fmaxf(tm, __shfl_xor_sync(0xffffffffu, tm, 2));
        tm = fmaxf(tm, __shfl_xor_sync(0xffffffffu, tm, 4));
        tm = fmaxf(tm, __shfl_xor_sync(0xffffffffu, tm, 8));
        float nmv = -tm * L2E;
        float te = 0.0f;
        #pragma unroll
        for (int jj = 0; jj < 8; jj++) te += ex2a(fmaf(ov[jj], L2E, nmv));
        te += __shfl_xor_sync(0xffffffffu, te, 1);
        te += __shfl_xor_sync(0xffffffffu, te, 2);
        te += __shfl_xor_sync(0xffffffffu, te, 4);
        te += __shfl_xor_sync(0xffffffffu, te, 8);
        if (tx == 0) g_part[((size_t)h * S_ + s) * 16 + blockIdx.x] = make_float2(tm, te);

        float* dp = attn + ((size_t)h * S_ + s) * S_ + t0 + 8 * tx;
        *(float4*)dp       = make_float4(ov[0], ov[1], ov[2], ov[3]);
        *(float4*)(dp + 4) = make_float4(ov[4], ov[5], ov[6], ov[7]);
    }
}

// ======== row reduce: combine 16 tile partials -> (M*log2e, 1/sum) per row =========
__global__ void rowred_kernel()
{
    int r = blockIdx.x * blockDim.x + threadIdx.x;
    if (r >= H_ * S_) return;
    const float2* p = g_part + (size_t)r * 16;
    float2 pv[16];
    #pragma unroll
    for (int i = 0; i < 16; i++) pv[i] = p[i];
    float M = pv[0].x;
    #pragma unroll
    for (int i = 1; i < 16; i++) M = fmaxf(M, pv[i].x);
    const float L2E = 1.4426950408889634f;
    float nm = -M * L2E;
    float SS = 0.0f;
    #pragma unroll
    for (int i = 0; i < 16; i++) SS += pv[i].y * ex2a(fmaf(pv[i].x, L2E, nm));
    g_rowm[r] = make_float2(M * L2E, 1.0f / SS);
}

// ======== standalone softmax (attn-only output case) ===============================
__device__ __forceinline__ u64 exp2_pair(float ylo, float yhi) {
    const float MAG = 12582912.0f;
    u64 y2 = pack2(ylo, yhi);
    u64 mag2 = pack2(MAG, MAG);
    u64 t2; asm("add.rn.f32x2 %0, %1, %2;" : "=l"(t2) : "l"(y2), "l"(mag2));
    float tlo, thi; unpack2(t2, tlo, thi);
    int nlo = __float_as_int(tlo) - 0x4B400000;
    int nhi = __float_as_int(thi) - 0x4B400000;
    u64 negone = pack2(-1.0f, -1.0f);
    u64 u2 = fma2n(mag2, negone, t2);
    u64 f2 = fma2n(u2, negone, y2);
    u64 p  = pack2(1.3333558146428443e-3f, 1.3333558146428443e-3f);
    p = fma2n(p, f2, pack2(9.618129107628477e-3f, 9.618129107628477e-3f));
    p = fma2n(p, f2, pack2(5.550410866482158e-2f, 5.550410866482158e-2f));
    p = fma2n(p, f2, pack2(2.402265069591007e-1f, 2.402265069591007e-1f));
    p = fma2n(p, f2, pack2(6.931471805599453e-1f, 6.931471805599453e-1f));
    p = fma2n(p, f2, pack2(1.0f, 1.0f));
    float plo, phi; unpack2(p, plo, phi);
    int rlo = __float_as_int(plo) + (nlo << 23);
    int rhi = __float_as_int(phi) + (nhi << 23);
    return pack2(__int_as_float(rlo), __int_as_float(rhi));
}

__global__ __launch_bounds__(256) void softmax_kernel(float* __restrict__ attn_arg)
{
    float* attn = attn_arg ? attn_arg : g_attn;
    float* x = attn + (size_t)blockIdx.x * S_;
    int tid = threadIdx.x;
    float4 a = *(const float4*)(x + 8 * tid);
    float4 b = *(const float4*)(x + 8 * tid + 4);
    float m = fmaxf(fmaxf(fmaxf(a.x, a.y), fmaxf(a.z, a.w)),
                    fmaxf(fmaxf(b.x, b.y), fmaxf(b.z, b.w)));
    __shared__ float red[8];
    #pragma unroll
    for (int off = 16; off; off >>= 1) m = fmaxf(m, __shfl_xor_sync(0xffffffffu, m, off));
    if ((tid & 31) == 0) red[tid >> 5] = m;
    __syncthreads();
    float mm = red[0];
    #pragma unroll
    for (int j = 1; j < 8; j++) mm = fmaxf(mm, red[j]);

    const float L2E = 1.4426950408889634f;
    float nm = -mm * L2E;
    float y0 = fmaf(a.x, L2E, nm), y1 = fmaf(a.y, L2E, nm);
    float y2 = fmaf(a.z, L2E, nm), y3 = fmaf(a.w, L2E, nm);
    float y4 = fmaf(b.x, L2E, nm), y5 = fmaf(b.y, L2E, nm);
    float y6 = fmaf(b.z, L2E, nm), y7 = fmaf(b.w, L2E, nm);

    float e0 = ex2a(y0), e1 = ex2a(y1), e2 = ex2a(y2), e3 = ex2a(y3);
    u64 r45 = exp2_pair(fmaxf(y4, -125.0f), fmaxf(y5, -125.0f));
    u64 r67 = exp2_pair(fmaxf(y6, -125.0f), fmaxf(y7, -125.0f));
    float e4, e5, e6, e7;
    unpack2(r45, e4, e5);
    unpack2(r67, e6, e7);

    float sum = ((e0 + e1) + (e2 + e3)) + ((e4 + e5) + (e6 + e7));
    #pragma unroll
    for (int off = 16; off; off >>= 1) sum += __shfl_xor_sync(0xffffffffu, sum, off);
    __syncthreads();
    if ((tid & 31) == 0) red[tid >> 5] = sum;
    __syncthreads();
    float ss = red[0];
    #pragma unroll
    for (int j = 1; j < 8; j++) ss += red[j];
    float inv = 1.0f / ss;

    *(float4*)(x + 8 * tid)     = make_float4(e0 * inv, e1 * inv, e2 * inv, e3 * inv);
    *(float4*)(x + 8 * tid + 4) = make_float4(e4 * inv, e5 * inv, e6 * inv, e7 * inv);
}

// ======== attn @ V split-k with inline softmax: grid (16, 12, 4) ===================
__global__ __launch_bounds__(128) void av_kernel(float* __restrict__ attn_arg, int write_attn)
{
    float* attn = attn_arg ? attn_arg : g_attn;
    __shared__ float AsT[2][16 * 132];
    __shared__ float Vs[2][16 * 68];
    int s0 = blockIdx.x * 128, h = blockIdx.y, z = blockIdx.z;
    int tid = threadIdx.x, tx = tid & 7, ty = tid >> 3;
    float* ab = attn + ((size_t)h * S_ + s0) * S_;
    const float* vb = g_vh + (size_t)h * S_ * DK_;
    u64 acc[8][4];
    #pragma unroll
    for (int i = 0; i < 8; i++)
        #pragma unroll
        for (int j = 0; j < 4; j++) acc[i][j] = 0ull;
    int vo = 8 * tx + ((tx >= 4) ? 4 : 0);
    const float L2E = 1.4426950408889634f;

    int la_s[4], la_c4[4];
    float nmL2[4], inv[4];
    #pragma unroll
    for (int it = 0; it < 4; it++) {
        int lin = tid + it * 128; la_s[it] = lin >> 2; la_c4[it] = lin & 3;
        float2 rp = g_rowm[h * S_ + s0 + la_s[it]];
        nmL2[it] = -rp.x; inv[it] = rp.y;
    }
    int lv_kx[2], lv_c4[2];
    #pragma unroll
    for (int it = 0; it < 2; it++) { int lin = tid + it * 128; lv_kx[it] = lin >> 4; lv_c4[it] = lin & 15; }

    int k0 = z * 512;
    float4 ra[4], rv[2];
    #pragma unroll
    for (int it = 0; it < 4; it++)
        ra[it] = *(const float4*)(ab + (size_t)la_s[it] * S_ + k0 + 4 * la_c4[it]);
    #pragma unroll
    for (int it = 0; it < 2; it++)
        rv[it] = *(const float4*)(vb + (size_t)(k0 + lv_kx[it]) * DK_ + 4 * lv_c4[it]);

    int buf = 0;
    for (int kki = 0; kki < 32; kki++) {
        #pragma unroll
        for (int it = 0; it < 4; it++) {
            float4 val = ra[it]; int s = la_s[it], c4 = la_c4[it];
            float4 p;
            p.x = ex2a(fmaf(val.x, L2E, nmL2[it])) * inv[it];
            p.y = ex2a(fmaf(val.y, L2E, nmL2[it])) * inv[it];
            p.z = ex2a(fmaf(val.z, L2E, nmL2[it])) * inv[it];
            p.w = ex2a(fmaf(val.w, L2E, nmL2[it])) * inv[it];
            AsT[buf][(4 * c4 + 0) * 132 + s] = p.x;
            AsT[buf][(4 * c4 + 1) * 132 + s] = p.y;
            AsT[buf][(4 * c4 + 2) * 132 + s] = p.z;
            AsT[buf][(4 * c4 + 3) * 132 + s] = p.w;
            if (write_attn)
                *(float4*)(ab + (size_t)s * S_ + (k0 + kki * 16) + 4 * c4) = p;
        }
        #pragma unroll
        for (int it = 0; it < 2; it++) {
            int c4 = lv_c4[it], dd = 4 * c4 + ((c4 >= 8) ? 4 : 0);
            *(float4*)(&Vs[buf][lv_kx[it] * 68 + dd]) = rv[it];
        }
        __syncthreads();

        if (kki < 31) {
            int kk = k0 + (kki + 1) * 16;
            #pragma unroll
            for (int it = 0; it < 4; it++)
                ra[it] = *(const float4*)(ab + (size_t)la_s[it] * S_ + kk + 4 * la_c4[it]);
            #pragma unroll
            for (int it = 0; it < 2; it++)
                rv[it] = *(const float4*)(vb + (size_t)(kk + lv_kx[it]) * DK_ + 4 * lv_c4[it]);
        }

        #pragma unroll 4
        for (int kx = 0; kx < 16; kx++) {
            float4 aa = *(const float4*)(&AsT[buf][kx * 132 + 8 * ty]);
            float4 ab4 = *(const float4*)(&AsT[buf][kx * 132 + 8 * ty + 4]);
            float4 va = *(const float4*)(&Vs[buf][kx * 68 + vo]);
            float4 vb4 = *(const float4*)(&Vs[buf][kx * 68 + vo + 4]);
            u64 ap[8] = { pack2(aa.x, aa.x), pack2(aa.y, aa.y), pack2(aa.z, aa.z), pack2(aa.w, aa.w),
                          pack2(ab4.x, ab4.x), pack2(ab4.y, ab4.y), pack2(ab4.z, ab4.z), pack2(ab4.w, ab4.w) };
            u64 vp[4] = { pack2(va.x, va.y), pack2(va.z, va.w), pack2(vb4.x, vb4.y), pack2(vb4.z, vb4.w) };
            #pragma unroll
            for (int i = 0; i < 8; i++)
                #pragma unroll
                for (int j = 0; j < 4; j++) fma2(acc[i][j], ap[i], vp[j]);
        }
        buf ^= 1;
    }

    #pragma unroll
    for (int i = 0; i < 8; i++) {
        int s = s0 + 8 * ty + i;
        float ov[8];
        #pragma unroll
        for (int j = 0; j < 4; j++) unpack2(acc[i][j], ov[2 * j], ov[2 * j + 1]);
        float* dp = g_opre + ((size_t)z * S_ + s) * DM_ + h * DK_ + 8 * tx;
        *(float4*)dp       = make_float4(ov[0], ov[1], ov[2], ov[3]);
        *(float4*)(dp + 4) = make_float4(ov[4], ov[5], ov[6], ov[7]);
    }
}

// ---------------- combine 4 AV partials into partial 0 -----------------------------
__global__ __launch_bounds__(256) void combine_kernel()
{
    size_t base = (size_t)blockIdx.x * blockDim.x * 2 + threadIdx.x;
    const size_t N = (size_t)S_ * DM_;
    #pragma unroll
    for (int rep = 0; rep < 2; rep++) {
        size_t idx = base + (size_t)rep * blockDim.x;
        float4 r0 = ((float4*)g_opre)[idx];
        float4 r1 = ((float4*)(g_opre + N))[idx];
        float4 r2 = ((float4*)(g_opre + 2 * N))[idx];
        float4 r3 = ((float4*)(g_opre + 3 * N))[idx];
        r0.x = (r0.x + r1.x) + (r2.x + r3.x);
        r0.y = (r0.y + r1.y) + (r2.y + r3.y);
        r0.z = (r0.z + r1.z) + (r2.z + r3.z);
        r0.w = (r0.w + r1.w) + (r2.w + r3.w);
        ((float4*)g_opre)[idx] = r0;
    }
}

// ---------------- host launcher -----------------------------------------------------
extern "C" void kernel_launch(void* const* d_in, const int* in_sizes, int n_in,
                              void* d_out, int out_size)
{
    const int QKV = 1572864, WMAT = 589824, VEC = 768;
    const float *q, *k, *v, *wq, *wk, *wv, *w_rk, *r_w, *r_r, *w_out, *b_out;
    if (n_in >= 11 && in_sizes[0] == VEC && in_sizes[1] == QKV && in_sizes[5] == QKV
        && in_sizes[6] == WMAT) {
        b_out = (const float*)d_in[0];
        k     = (const float*)d_in[1];
        q     = (const float*)d_in[2];
        r_r   = (const float*)d_in[3];
        r_w   = (const float*)d_in[4];
        v     = (const float*)d_in[5];
        w_out = (const float*)d_in[6];
        w_rk  = (const float*)d_in[7];
        wk    = (const float*)d_in[8];
        wq    = (const float*)d_in[9];
        wv    = (const float*)d_in[10];
    } else {
        q     = (const float*)d_in[0];
        k     = (const float*)d_in[1];
        v     = (const float*)d_in[2];
        wq    = (const float*)d_in[3];
        wk    = (const float*)d_in[4];
        wv    = (const float*)d_in[5];
        w_rk  = (const float*)d_in[6];
        r_w   = (const float*)d_in[7];
        r_r   = (const float*)d_in[8];
        w_out = (const float*)d_in[9];
        b_out = (const float*)d_in[10];
    }

    const long long OUT_E  = (long long)S_ * DM_;
    const long long ATTN_E = (long long)H_ * S_ * S_;
    long long os = (long long)out_size;

    float* out_ptr  = (float*)d_out;
    float* attn_ptr = nullptr;
    bool need_out = true;

    if (os >= OUT_E + ATTN_E) {
        attn_ptr = (float*)d_out + OUT_E;
    } else if (os == ATTN_E) {
        attn_ptr = (float*)d_out;
        need_out = false;
    }

    pe_const_kernel<<<8, 256>>>();
    pe_gmax_kernel<<<1, 128>>>();
    pe_table_kernel<<<1024, 256>>>();
    pe_fill_kernel<<<2048, 256>>>();

    proj_all_kernel<<<dim3(12, 32, 4), 128>>>(q, k, v, wq, wk, wv, w_rk);

    bias_kernel<<<(((H_ * (S_ + J_)) * 32) + 255) / 256, 256>>>(r_w, r_r);

    logits_kernel<<<dim3(16, 16, 12), 256>>>(attn_ptr);

    if (need_out) {
        rowred_kernel<<<96, 256>>>();
        av_kernel<<<dim3(16, 12, 4), 128>>>(attn_ptr, attn_ptr ? 1 : 0);
        combine_kernel<<<768, 256>>>();
        gemm_bias_kernel<<<dim3(12, 16), 128>>>(w_out, b_out, out_ptr);
    } else {
        softmax_kernel<<<H_ * S_, 256>>>(attn_ptr);
    }
}